// round 2
// baseline (speedup 1.0000x reference)
#include <cuda_runtime.h>

#define IN_F   8192
#define OUT_F  8192
#define BATCH  2048

#define NCHUNK 8
#define CCOLS  1024                 // cols per chunk = 256 threads * float4
#define NSPLIT 128                  // row splits per chunk
#define RSPLIT (OUT_F / NSPLIT)     // 64 rows per W ticket
#define GRP    16                   // batches per G/F ticket
#define NGRP   (BATCH / GRP)        // 128

#define NBLOCKS 1184                // 148 SMs * 8

// ---- scratch (rewritten every call before being read -> deterministic) ----
__device__ float g_part[NSPLIT * IN_F];     // 4 MB partial colsums
__device__ float g_colsum[IN_F];
__device__ float g_dot[NCHUNK * BATCH];     // per-chunk dot partials
__device__ float g_bias;
// ---- control (re-zeroed by k_init every call) ----
__device__ int g_ticket;
__device__ int g_cntW[NCHUNK];
__device__ int g_readyR[NCHUNK];
__device__ int g_cntB[NGRP];
__device__ int g_readyB;

// Ticket layout:
//   0                     : bias sum
//   per chunk c (0..7)    : NSPLIT W tickets, 1 R ticket, NGRP G tickets
//   tail                  : NGRP F tickets
#define PER_CHUNK (NSPLIT + 1 + NGRP)          // 257
#define T_F0      (1 + NCHUNK * PER_CHUNK)     // 2057
#define T_TOTAL   (T_F0 + NGRP)                // 2185

__global__ void k_init()
{
    int t = threadIdx.x;
    if (t == 0) { g_ticket = 0; g_readyB = 0; }
    if (t < NCHUNK) { g_cntW[t] = 0; g_readyR[t] = 0; }
    if (t < NGRP)   { g_cntB[t] = 0; }
}

__global__ __launch_bounds__(256, 8) void k_fused(const float* __restrict__ x,
                                                  const float* __restrict__ weight,
                                                  const float* __restrict__ bias,
                                                  float* __restrict__ y)
{
    __shared__ int   s_t;
    __shared__ float sh[256];
    const int tid = threadIdx.x;

    for (;;) {
        if (tid == 0) s_t = atomicAdd(&g_ticket, 1);
        __syncthreads();
        const int t = s_t;
        if (t >= T_TOTAL) return;

        if (t == 0) {
            // ---- bias sum ----
            float s = 0.f;
            #pragma unroll
            for (int k = 0; k < IN_F / 256; ++k) s += bias[tid + k * 256];
            sh[tid] = s; __syncthreads();
            for (int o = 128; o >= 32; o >>= 1) { if (tid < o) sh[tid] += sh[tid + o]; __syncthreads(); }
            if (tid < 32) {
                float v = sh[tid];
                #pragma unroll
                for (int o = 16; o > 0; o >>= 1) v += __shfl_down_sync(0xffffffffu, v, o);
                if (tid == 0) { g_bias = v; __threadfence(); atomicExch(&g_readyB, 1); }
            }
        } else if (t < T_F0) {
            const int u     = t - 1;
            const int chunk = u / PER_CHUNK;
            const int r     = u % PER_CHUNK;

            if (r < NSPLIT) {
                // ---- W: partial colsum of 64 rows x 1024 cols ----
                const int split = r;
                const int col   = chunk * CCOLS + (tid << 2);
                const float4* wp = reinterpret_cast<const float4*>(
                    weight + (size_t)split * RSPLIT * IN_F + col);
                float4 a = make_float4(0.f, 0.f, 0.f, 0.f);
                #pragma unroll 8
                for (int rr = 0; rr < RSPLIT; ++rr) {
                    float4 v = wp[(size_t)rr * (IN_F / 4)];
                    a.x += v.x; a.y += v.y; a.z += v.z; a.w += v.w;
                }
                *reinterpret_cast<float4*>(g_part + (size_t)split * IN_F + col) = a;
                __threadfence();
                __syncthreads();
                if (tid == 0) atomicAdd(&g_cntW[chunk], 1);
            } else if (r == NSPLIT) {
                // ---- R: reduce 128 partials -> g_colsum[chunk] ----
                if (tid == 0)
                    while (((volatile int*)g_cntW)[chunk] < NSPLIT) __nanosleep(128);
                __syncthreads();
                __threadfence();
                const int col = chunk * CCOLS + (tid << 2);
                float4 a = make_float4(0.f, 0.f, 0.f, 0.f);
                #pragma unroll 4
                for (int p = 0; p < NSPLIT; ++p) {
                    float4 v = *reinterpret_cast<const float4*>(g_part + (size_t)p * IN_F + col);
                    a.x += v.x; a.y += v.y; a.z += v.z; a.w += v.w;
                }
                *reinterpret_cast<float4*>(g_colsum + col) = a;
                __threadfence();
                __syncthreads();
                if (tid == 0) atomicExch(&g_readyR[chunk], 1);
            } else {
                // ---- G: per-chunk dot for 16 batch rows ----
                const int grp = r - NSPLIT - 1;
                if (tid == 0)
                    while (((volatile int*)g_readyR)[chunk] == 0) __nanosleep(128);
                __syncthreads();
                __threadfence();
                const int warp = tid >> 5, lane = tid & 31;
                const float4* cp = reinterpret_cast<const float4*>(g_colsum + chunk * CCOLS);
                #pragma unroll
                for (int i = 0; i < 2; ++i) {                 // 8 warps * 2 rows = 16 rows
                    const int row = grp * GRP + warp * 2 + i;
                    const float4* xp = reinterpret_cast<const float4*>(
                        x + (size_t)row * IN_F + chunk * CCOLS);
                    float acc = 0.f;
                    #pragma unroll
                    for (int k = 0; k < 8; ++k) {             // 32 lanes * 8 = 256 float4
                        float4 xv = xp[lane + k * 32];
                        float4 cv = cp[lane + k * 32];
                        acc += xv.x * cv.x + xv.y * cv.y + xv.z * cv.z + xv.w * cv.w;
                    }
                    #pragma unroll
                    for (int o = 16; o > 0; o >>= 1) acc += __shfl_down_sync(0xffffffffu, acc, o);
                    if (lane == 0) g_dot[chunk * BATCH + row] = acc;
                }
                __threadfence();
                __syncthreads();
                if (tid == 0) atomicAdd(&g_cntB[grp], 1);
            }
        } else {
            // ---- F: final sum over chunks + bias for 16 batches ----
            const int grp = t - T_F0;
            if (tid == 0) {
                while (((volatile int*)g_cntB)[grp] < NCHUNK) __nanosleep(128);
                while (*((volatile int*)&g_readyB) == 0)      __nanosleep(128);
            }
            __syncthreads();
            __threadfence();
            if (tid < GRP) {
                const int b = grp * GRP + tid;
                float s = g_bias;
                #pragma unroll
                for (int c = 0; c < NCHUNK; ++c) s += g_dot[c * BATCH + b];
                y[b] = s;
            }
        }
        __syncthreads();   // protect s_t before next claim
    }
}

// ---------------------------------------------------------------------------
extern "C" void kernel_launch(void* const* d_in, const int* in_sizes, int n_in,
                              void* d_out, int out_size)
{
    const float* x      = (const float*)d_in[0];   // (2048, 8192)
    const float* weight = (const float*)d_in[1];   // (8192, 8192)
    const float* bias   = (const float*)d_in[2];   // (8192,)
    float* y            = (float*)d_out;           // (2048, 1)

    k_init<<<1, 256>>>();
    k_fused<<<NBLOCKS, 256>>>(x, weight, bias, y);
}

// round 3
// speedup vs baseline: 1.0047x; 1.0047x over previous
#include <cuda_runtime.h>

#define IN_F   8192
#define OUT_F  8192
#define BATCH  2048

#define NCHUNK 8
#define CCOLS  1024                 // cols per chunk = 256 threads * float4
#define NSPLIT 128                  // row splits per chunk
#define RSPLIT (OUT_F / NSPLIT)     // 64 rows per W ticket
#define GRP    16                   // batches per G/F ticket
#define NGRP   (BATCH / GRP)        // 128

#define NBLOCKS 1184                // 148 SMs * 8

// ---- scratch (rewritten every call before being read -> deterministic) ----
__device__ float g_part[NSPLIT * IN_F];     // 4 MB partial colsums
__device__ float g_colsum[IN_F];
__device__ float g_dot[NCHUNK * BATCH];     // per-chunk dot partials
__device__ float g_bias;
// ---- control (re-zeroed by k_init every call) ----
__device__ int g_ticket;
__device__ int g_cntW[NCHUNK];
__device__ int g_readyR[NCHUNK];
__device__ int g_cntB[NGRP];
__device__ int g_readyB;

// Ticket layout:
//   0                     : bias sum
//   per chunk c (0..7)    : NSPLIT W tickets, 1 R ticket, NGRP G tickets
//   tail                  : NGRP F tickets
#define PER_CHUNK (NSPLIT + 1 + NGRP)          // 257
#define T_F0      (1 + NCHUNK * PER_CHUNK)     // 2057
#define T_TOTAL   (T_F0 + NGRP)                // 2185

__global__ void k_init()
{
    int t = threadIdx.x;
    if (t == 0) { g_ticket = 0; g_readyB = 0; }
    if (t < NCHUNK) { g_cntW[t] = 0; g_readyR[t] = 0; }
    if (t < NGRP)   { g_cntB[t] = 0; }
}

__global__ __launch_bounds__(256, 8) void k_fused(const float* __restrict__ x,
                                                  const float* __restrict__ weight,
                                                  const float* __restrict__ bias,
                                                  float* __restrict__ y)
{
    __shared__ int   s_t;
    __shared__ float sh[256];
    const int tid = threadIdx.x;

    for (;;) {
        if (tid == 0) s_t = atomicAdd(&g_ticket, 1);
        __syncthreads();
        const int t = s_t;
        if (t >= T_TOTAL) return;

        if (t == 0) {
            // ---- bias sum ----
            float s = 0.f;
            #pragma unroll
            for (int k = 0; k < IN_F / 256; ++k) s += bias[tid + k * 256];
            sh[tid] = s; __syncthreads();
            for (int o = 128; o >= 32; o >>= 1) { if (tid < o) sh[tid] += sh[tid + o]; __syncthreads(); }
            if (tid < 32) {
                float v = sh[tid];
                #pragma unroll
                for (int o = 16; o > 0; o >>= 1) v += __shfl_down_sync(0xffffffffu, v, o);
                if (tid == 0) { g_bias = v; __threadfence(); atomicExch(&g_readyB, 1); }
            }
        } else if (t < T_F0) {
            const int u     = t - 1;
            const int chunk = u / PER_CHUNK;
            const int r     = u % PER_CHUNK;

            if (r < NSPLIT) {
                // ---- W: partial colsum of 64 rows x 1024 cols ----
                const int split = r;
                const int col   = chunk * CCOLS + (tid << 2);
                const float4* wp = reinterpret_cast<const float4*>(
                    weight + (size_t)split * RSPLIT * IN_F + col);
                float4 a = make_float4(0.f, 0.f, 0.f, 0.f);
                #pragma unroll 8
                for (int rr = 0; rr < RSPLIT; ++rr) {
                    float4 v = wp[(size_t)rr * (IN_F / 4)];
                    a.x += v.x; a.y += v.y; a.z += v.z; a.w += v.w;
                }
                *reinterpret_cast<float4*>(g_part + (size_t)split * IN_F + col) = a;
                __threadfence();
                __syncthreads();
                if (tid == 0) atomicAdd(&g_cntW[chunk], 1);
            } else if (r == NSPLIT) {
                // ---- R: reduce 128 partials -> g_colsum[chunk] ----
                if (tid == 0)
                    while (((volatile int*)g_cntW)[chunk] < NSPLIT) __nanosleep(128);
                __syncthreads();
                __threadfence();
                const int col = chunk * CCOLS + (tid << 2);
                float4 a = make_float4(0.f, 0.f, 0.f, 0.f);
                #pragma unroll 4
                for (int p = 0; p < NSPLIT; ++p) {
                    float4 v = *reinterpret_cast<const float4*>(g_part + (size_t)p * IN_F + col);
                    a.x += v.x; a.y += v.y; a.z += v.z; a.w += v.w;
                }
                *reinterpret_cast<float4*>(g_colsum + col) = a;
                __threadfence();
                __syncthreads();
                if (tid == 0) atomicExch(&g_readyR[chunk], 1);
            } else {
                // ---- G: per-chunk dot for 16 batch rows ----
                const int grp = r - NSPLIT - 1;
                if (tid == 0)
                    while (((volatile int*)g_readyR)[chunk] == 0) __nanosleep(128);
                __syncthreads();
                __threadfence();
                const int warp = tid >> 5, lane = tid & 31;
                const float4* cp = reinterpret_cast<const float4*>(g_colsum + chunk * CCOLS);
                #pragma unroll
                for (int i = 0; i < 2; ++i) {                 // 8 warps * 2 rows = 16 rows
                    const int row = grp * GRP + warp * 2 + i;
                    const float4* xp = reinterpret_cast<const float4*>(
                        x + (size_t)row * IN_F + chunk * CCOLS);
                    float acc = 0.f;
                    #pragma unroll
                    for (int k = 0; k < 8; ++k) {             // 32 lanes * 8 = 256 float4
                        float4 xv = xp[lane + k * 32];
                        float4 cv = cp[lane + k * 32];
                        acc += xv.x * cv.x + xv.y * cv.y + xv.z * cv.z + xv.w * cv.w;
                    }
                    #pragma unroll
                    for (int o = 16; o > 0; o >>= 1) acc += __shfl_down_sync(0xffffffffu, acc, o);
                    if (lane == 0) g_dot[chunk * BATCH + row] = acc;
                }
                __threadfence();
                __syncthreads();
                if (tid == 0) atomicAdd(&g_cntB[grp], 1);
            }
        } else {
            // ---- F: final sum over chunks + bias for 16 batches ----
            const int grp = t - T_F0;
            if (tid == 0) {
                while (((volatile int*)g_cntB)[grp] < NCHUNK) __nanosleep(128);
                while (*((volatile int*)&g_readyB) == 0)      __nanosleep(128);
            }
            __syncthreads();
            __threadfence();
            if (tid < GRP) {
                const int b = grp * GRP + tid;
                float s = g_bias;
                #pragma unroll
                for (int c = 0; c < NCHUNK; ++c) s += g_dot[c * BATCH + b];
                y[b] = s;
            }
        }
        __syncthreads();   // protect s_t before next claim
    }
}

// ---------------------------------------------------------------------------
extern "C" void kernel_launch(void* const* d_in, const int* in_sizes, int n_in,
                              void* d_out, int out_size)
{
    const float* x      = (const float*)d_in[0];   // (2048, 8192)
    const float* weight = (const float*)d_in[1];   // (8192, 8192)
    const float* bias   = (const float*)d_in[2];   // (8192,)
    float* y            = (float*)d_out;           // (2048, 1)

    k_init<<<1, 256>>>();
    k_fused<<<NBLOCKS, 256>>>(x, weight, bias, y);
}

// round 4
// speedup vs baseline: 1.0068x; 1.0022x over previous
#include <cuda_runtime.h>

#define IN_F   8192
#define OUT_F  8192
#define BATCH  2048

#define NCHUNK 8
#define CCOLS  1024                 // cols per chunk = 256 threads * float4
#define NSPLIT 128                  // row splits per chunk
#define RSPLIT (OUT_F / NSPLIT)     // 64 rows per W ticket
#define GRP    16                   // batches per G/F ticket
#define NGRP   (BATCH / GRP)        // 128

#define NBLOCKS 1184                // 148 SMs * 8

// ---- scratch (rewritten every call before being read -> deterministic) ----
__device__ float g_part[NSPLIT * IN_F];     // 4 MB partial colsums
__device__ float g_colsum[IN_F];
__device__ float g_dot[NCHUNK * BATCH];     // per-chunk dot partials
__device__ float g_bias;
// ---- control (re-zeroed by k_init every call) ----
__device__ int g_ticket;
__device__ int g_cntW[NCHUNK];
__device__ int g_readyR[NCHUNK];
__device__ int g_cntB[NGRP];
__device__ int g_readyB;

// Ticket layout:
//   0                     : bias sum
//   per chunk c (0..7)    : NSPLIT W tickets, 1 R ticket, NGRP G tickets
//   tail                  : NGRP F tickets
#define PER_CHUNK (NSPLIT + 1 + NGRP)          // 257
#define T_F0      (1 + NCHUNK * PER_CHUNK)     // 2057
#define T_TOTAL   (T_F0 + NGRP)                // 2185

__global__ void k_init()
{
    int t = threadIdx.x;
    if (t == 0) { g_ticket = 0; g_readyB = 0; }
    if (t < NCHUNK) { g_cntW[t] = 0; g_readyR[t] = 0; }
    if (t < NGRP)   { g_cntB[t] = 0; }
}

__global__ __launch_bounds__(256, 8) void k_fused(const float* __restrict__ x,
                                                  const float* __restrict__ weight,
                                                  const float* __restrict__ bias,
                                                  float* __restrict__ y)
{
    __shared__ int   s_t;
    __shared__ float sh[256];
    const int tid = threadIdx.x;

    for (;;) {
        if (tid == 0) s_t = atomicAdd(&g_ticket, 1);
        __syncthreads();
        const int t = s_t;
        if (t >= T_TOTAL) return;

        if (t == 0) {
            // ---- bias sum ----
            float s = 0.f;
            #pragma unroll
            for (int k = 0; k < IN_F / 256; ++k) s += bias[tid + k * 256];
            sh[tid] = s; __syncthreads();
            for (int o = 128; o >= 32; o >>= 1) { if (tid < o) sh[tid] += sh[tid + o]; __syncthreads(); }
            if (tid < 32) {
                float v = sh[tid];
                #pragma unroll
                for (int o = 16; o > 0; o >>= 1) v += __shfl_down_sync(0xffffffffu, v, o);
                if (tid == 0) { g_bias = v; __threadfence(); atomicExch(&g_readyB, 1); }
            }
        } else if (t < T_F0) {
            const int u     = t - 1;
            const int chunk = u / PER_CHUNK;
            const int r     = u % PER_CHUNK;

            if (r < NSPLIT) {
                // ---- W: partial colsum of 64 rows x 1024 cols ----
                const int split = r;
                const int col   = chunk * CCOLS + (tid << 2);
                const float4* wp = reinterpret_cast<const float4*>(
                    weight + (size_t)split * RSPLIT * IN_F + col);
                float4 a = make_float4(0.f, 0.f, 0.f, 0.f);
                #pragma unroll 8
                for (int rr = 0; rr < RSPLIT; ++rr) {
                    float4 v = wp[(size_t)rr * (IN_F / 4)];
                    a.x += v.x; a.y += v.y; a.z += v.z; a.w += v.w;
                }
                *reinterpret_cast<float4*>(g_part + (size_t)split * IN_F + col) = a;
                __threadfence();
                __syncthreads();
                if (tid == 0) atomicAdd(&g_cntW[chunk], 1);
            } else if (r == NSPLIT) {
                // ---- R: reduce 128 partials -> g_colsum[chunk] ----
                if (tid == 0)
                    while (((volatile int*)g_cntW)[chunk] < NSPLIT) __nanosleep(128);
                __syncthreads();
                __threadfence();
                const int col = chunk * CCOLS + (tid << 2);
                float4 a = make_float4(0.f, 0.f, 0.f, 0.f);
                #pragma unroll 4
                for (int p = 0; p < NSPLIT; ++p) {
                    float4 v = *reinterpret_cast<const float4*>(g_part + (size_t)p * IN_F + col);
                    a.x += v.x; a.y += v.y; a.z += v.z; a.w += v.w;
                }
                *reinterpret_cast<float4*>(g_colsum + col) = a;
                __threadfence();
                __syncthreads();
                if (tid == 0) atomicExch(&g_readyR[chunk], 1);
            } else {
                // ---- G: per-chunk dot for 16 batch rows ----
                const int grp = r - NSPLIT - 1;
                if (tid == 0)
                    while (((volatile int*)g_readyR)[chunk] == 0) __nanosleep(128);
                __syncthreads();
                __threadfence();
                const int warp = tid >> 5, lane = tid & 31;
                const float4* cp = reinterpret_cast<const float4*>(g_colsum + chunk * CCOLS);
                #pragma unroll
                for (int i = 0; i < 2; ++i) {                 // 8 warps * 2 rows = 16 rows
                    const int row = grp * GRP + warp * 2 + i;
                    const float4* xp = reinterpret_cast<const float4*>(
                        x + (size_t)row * IN_F + chunk * CCOLS);
                    float acc = 0.f;
                    #pragma unroll
                    for (int k = 0; k < 8; ++k) {             // 32 lanes * 8 = 256 float4
                        float4 xv = xp[lane + k * 32];
                        float4 cv = cp[lane + k * 32];
                        acc += xv.x * cv.x + xv.y * cv.y + xv.z * cv.z + xv.w * cv.w;
                    }
                    #pragma unroll
                    for (int o = 16; o > 0; o >>= 1) acc += __shfl_down_sync(0xffffffffu, acc, o);
                    if (lane == 0) g_dot[chunk * BATCH + row] = acc;
                }
                __threadfence();
                __syncthreads();
                if (tid == 0) atomicAdd(&g_cntB[grp], 1);
            }
        } else {
            // ---- F: final sum over chunks + bias for 16 batches ----
            const int grp = t - T_F0;
            if (tid == 0) {
                while (((volatile int*)g_cntB)[grp] < NCHUNK) __nanosleep(128);
                while (*((volatile int*)&g_readyB) == 0)      __nanosleep(128);
            }
            __syncthreads();
            __threadfence();
            if (tid < GRP) {
                const int b = grp * GRP + tid;
                float s = g_bias;
                #pragma unroll
                for (int c = 0; c < NCHUNK; ++c) s += g_dot[c * BATCH + b];
                y[b] = s;
            }
        }
        __syncthreads();   // protect s_t before next claim
    }
}

// ---------------------------------------------------------------------------
extern "C" void kernel_launch(void* const* d_in, const int* in_sizes, int n_in,
                              void* d_out, int out_size)
{
    const float* x      = (const float*)d_in[0];   // (2048, 8192)
    const float* weight = (const float*)d_in[1];   // (8192, 8192)
    const float* bias   = (const float*)d_in[2];   // (8192,)
    float* y            = (float*)d_out;           // (2048, 1)

    k_init<<<1, 256>>>();
    k_fused<<<NBLOCKS, 256>>>(x, weight, bias, y);
}